// round 14
// baseline (speedup 1.0000x reference)
#include <cuda_runtime.h>
#include <cuda_bf16.h>
#include <cstdint>

typedef unsigned int u32;
typedef unsigned long long u64;

#define BB   8
#define CIN  512
#define MIDC 128
#define NNE  2304
#define SCALE_S 0.08838834764831845f
#define SCALE_E 0.125f
#define INV_OSCALE (1.0f/2048.0f)

// ---------------- scratch layout (bytes) ----------------
#define XT_SZ   ((size_t)3*BB*NNE*CIN*2)
#define FT_ONE  ((size_t)BB*NNE*MIDC)       // fp8
#define G_SZ    ((size_t)2*BB*MIDC*NNE*2)   // bf16
#define GN_SZ   ((size_t)2*BB*MIDC*NNE)     // fp8
#define ET_SZ   ((size_t)2*BB*NNE*NNE)      // fp8
#define Z_SZ    ((size_t)2*BB*NNE*4)
#define OT_SZ   ((size_t)2*BB*NNE*MIDC*2)
#define WC_SZ   ((size_t)6*65536*2)

#define XT_OFF  0ull
#define FT_OFF  (XT_OFF + XT_SZ)
#define G_OFF   (FT_OFF + 3*FT_ONE)
#define GN_OFF  (G_OFF + G_SZ)
#define ET_OFF  (GN_OFF + GN_SZ)
#define Z_OFF   (ET_OFF + ET_SZ)
#define OT_OFF  (Z_OFF + Z_SZ)
#define WC_OFF  (OT_OFF + OT_SZ)
#define TOTAL_SCRATCH (WC_OFF + WC_SZ)

__device__ __align__(1024) char d_scratch[TOTAL_SCRATCH];

// ---------------- MMA building blocks ----------------
__device__ __forceinline__ u32 pack_bf16(float lo, float hi) {
    u32 r; asm("cvt.rn.bf16x2.f32 %0, %1, %2;" : "=r"(r) : "f"(hi), "f"(lo)); return r;
}
__device__ __forceinline__ unsigned short pack_e4m3(float lo, float hi) {
    unsigned short r;
    asm("cvt.rn.satfinite.e4m3x2.f32 %0, %1, %2;" : "=h"(r) : "f"(hi), "f"(lo));
    return r;
}
__device__ __forceinline__ void cpasync16(u32 saddr, const void* g) {
    asm volatile("cp.async.cg.shared.global [%0], [%1], 16;" :: "r"(saddr), "l"(g));
}
#define CP_COMMIT() asm volatile("cp.async.commit_group;" ::: "memory")

__device__ __forceinline__ void ldsm_x4(u32 a, u32& r0, u32& r1, u32& r2, u32& r3) {
    asm volatile("ldmatrix.sync.aligned.m8n8.x4.shared.b16 {%0,%1,%2,%3}, [%4];"
                 : "=r"(r0), "=r"(r1), "=r"(r2), "=r"(r3) : "r"(a));
}
__device__ __forceinline__ void mma16816(float c[4], const u32 a[4], u32 b0, u32 b1) {
    asm volatile("mma.sync.aligned.m16n8k16.row.col.f32.bf16.bf16.f32 "
                 "{%0,%1,%2,%3}, {%4,%5,%6,%7}, {%8,%9}, {%0,%1,%2,%3};"
                 : "+f"(c[0]), "+f"(c[1]), "+f"(c[2]), "+f"(c[3])
                 : "r"(a[0]), "r"(a[1]), "r"(a[2]), "r"(a[3]), "r"(b0), "r"(b1));
}
__device__ __forceinline__ void mma16832_fp8(float c[4], const u32 a[4], u32 b0, u32 b1) {
    asm volatile("mma.sync.aligned.m16n8k32.row.col.f32.e4m3.e4m3.f32 "
                 "{%0,%1,%2,%3}, {%4,%5,%6,%7}, {%8,%9}, {%0,%1,%2,%3};"
                 : "+f"(c[0]), "+f"(c[1]), "+f"(c[2]), "+f"(c[3])
                 : "r"(a[0]), "r"(a[1]), "r"(a[2]), "r"(a[3]), "r"(b0), "r"(b1));
}

// Tile: 128 rows x 128 B. 8 x 16B chunks/row. Swizzle cc = c ^ (r&7).
#define TILE_B 16384
#define NSTAGE 3

__device__ __forceinline__ u32 sw64(int r, int ch) {
    return (u32)(r * 128 + ((ch ^ (r & 7)) << 4));
}

__device__ __forceinline__ void tile_load(u32 sdst, const char* src,
                                          size_t pitchB, int k0B, int tid) {
    int r = tid >> 1;
    const char* g = src + (size_t)r * pitchB + k0B;
#pragma unroll
    for (int i = 0; i < 4; i++) {
        int c = (tid & 1) * 4 + i;
        cpasync16(sdst + sw64(r, c), g + c * 16);
    }
}

// CTA 128x128 bf16 GEMM
__device__ __forceinline__ void hmma_gemm(
    u32 sA, u32 sB,
    const __nv_bfloat16* __restrict__ A, size_t pA,
    const __nv_bfloat16* __restrict__ B, size_t pB,
    int Kd, int tid, float acc[4][4][4])
{
#pragma unroll
    for (int i = 0; i < 4; i++)
#pragma unroll
        for (int j = 0; j < 4; j++)
#pragma unroll
            for (int e = 0; e < 4; e++) acc[i][j][e] = 0.f;

    const int lane = tid & 31, wid = tid >> 5;
    const int wm = wid & 1, wn = wid >> 1;
    const int T = Kd / 64;
    const char* Ab = (const char*)A;
    const char* Bb = (const char*)B;
    const size_t pAB = pA * 2, pBB = pB * 2;

    tile_load(sA, Ab, pAB, 0, tid);
    tile_load(sB, Bb, pBB, 0, tid);
    CP_COMMIT();
    if (T > 1) {
        tile_load(sA + TILE_B, Ab, pAB, 128, tid);
        tile_load(sB + TILE_B, Bb, pBB, 128, tid);
    }
    CP_COMMIT();

    int slot_next = 2 % NSTAGE;
    for (int t = 0; t < T; t++) {
        asm volatile("cp.async.wait_group 1;" ::: "memory");
        __syncthreads();
        if (t + 2 < T) {
            tile_load(sA + slot_next * TILE_B, Ab, pAB, (t + 2) * 128, tid);
            tile_load(sB + slot_next * TILE_B, Bb, pBB, (t + 2) * 128, tid);
        }
        CP_COMMIT();
        slot_next = (slot_next + 1 == NSTAGE) ? 0 : slot_next + 1;

        const int cur = t % NSTAGE;
        const u32 abuf = sA + cur * TILE_B;
        const u32 bbuf = sB + cur * TILE_B;
#pragma unroll
        for (int k16 = 0; k16 < 4; k16++) {
            u32 a[4][4];
#pragma unroll
            for (int f = 0; f < 4; f++) {
                int row = wm * 64 + f * 16 + (lane & 15);
                int ch  = k16 * 2 + (lane >> 4);
                ldsm_x4(abuf + sw64(row, ch), a[f][0], a[f][1], a[f][2], a[f][3]);
            }
            u32 b[4][2];
#pragma unroll
            for (int p = 0; p < 2; p++) {
                int row = wn * 32 + p * 16 + ((lane & 16) >> 1) + (lane & 7);
                int ch  = k16 * 2 + ((lane >> 3) & 1);
                ldsm_x4(bbuf + sw64(row, ch), b[2 * p][0], b[2 * p][1],
                        b[2 * p + 1][0], b[2 * p + 1][1]);
            }
#pragma unroll
            for (int mf = 0; mf < 4; mf++)
#pragma unroll
                for (int nf = 0; nf < 4; nf++)
                    mma16816(acc[mf][nf], a[mf], b[nf][0], b[nf][1]);
        }
    }
}

// CTA 128x128 FP8 GEMM (streamed K)
__device__ __forceinline__ void qmma_gemm(
    u32 sA, u32 sB,
    const char* __restrict__ A, size_t pAB,
    const char* __restrict__ B, size_t pBB,
    int KdB, int tid, float acc[4][4][4])
{
#pragma unroll
    for (int i = 0; i < 4; i++)
#pragma unroll
        for (int j = 0; j < 4; j++)
#pragma unroll
            for (int e = 0; e < 4; e++) acc[i][j][e] = 0.f;

    const int lane = tid & 31, wid = tid >> 5;
    const int wm = wid & 1, wn = wid >> 1;
    const int T = KdB / 128;

    tile_load(sA, A, pAB, 0, tid);
    tile_load(sB, B, pBB, 0, tid);
    CP_COMMIT();
    if (T > 1) {
        tile_load(sA + TILE_B, A, pAB, 128, tid);
        tile_load(sB + TILE_B, B, pBB, 128, tid);
    }
    CP_COMMIT();

    int slot_next = 2 % NSTAGE;
    for (int t = 0; t < T; t++) {
        asm volatile("cp.async.wait_group 1;" ::: "memory");
        __syncthreads();
        if (t + 2 < T) {
            tile_load(sA + slot_next * TILE_B, A, pAB, (t + 2) * 128, tid);
            tile_load(sB + slot_next * TILE_B, B, pBB, (t + 2) * 128, tid);
        }
        CP_COMMIT();
        slot_next = (slot_next + 1 == NSTAGE) ? 0 : slot_next + 1;

        const int cur = t % NSTAGE;
        const u32 abuf = sA + cur * TILE_B;
        const u32 bbuf = sB + cur * TILE_B;
#pragma unroll
        for (int k32 = 0; k32 < 4; k32++) {
            u32 a[4][4];
#pragma unroll
            for (int f = 0; f < 4; f++) {
                int row = wm * 64 + f * 16 + (lane & 15);
                int ch  = k32 * 2 + (lane >> 4);
                ldsm_x4(abuf + sw64(row, ch), a[f][0], a[f][1], a[f][2], a[f][3]);
            }
            u32 b[4][2];
#pragma unroll
            for (int p = 0; p < 2; p++) {
                int row = wn * 32 + p * 16 + ((lane & 16) >> 1) + (lane & 7);
                int ch  = k32 * 2 + ((lane >> 3) & 1);
                ldsm_x4(bbuf + sw64(row, ch), b[2 * p][0], b[2 * p][1],
                        b[2 * p + 1][0], b[2 * p + 1][1]);
            }
#pragma unroll
            for (int mf = 0; mf < 4; mf++)
#pragma unroll
                for (int nf = 0; nf < 4; nf++)
                    mma16832_fp8(acc[mf][nf], a[mf], b[nf][0], b[nf][1]);
        }
    }
}

#define SMEM_DYN   (2 * NSTAGE * TILE_B)   // 96 KB
#define SMEM_SCORE (4 * TILE_B)            // 64 KB: A + 3 B slots

// ============================ SIMT prep ============================
__global__ __launch_bounds__(256) void transpose_x(
    const float* __restrict__ x, const float* __restrict__ x_v,
    const float* __restrict__ x_h, __nv_bfloat16* __restrict__ xT)
{
    __shared__ float t[32][33];
    int z = blockIdx.z, tt = z >> 3, b = z & 7;
    const float* src = (tt == 0) ? x : (tt == 1 ? x_v : x_h);
    int n0 = blockIdx.x * 32, c0 = blockIdx.y * 32;
    int tx = threadIdx.x & 31, ty8 = threadIdx.x >> 5;
#pragma unroll
    for (int i = 0; i < 4; i++)
        t[ty8 + i * 8][tx] = src[((size_t)b * CIN + c0 + ty8 + i * 8) * NNE + n0 + tx];
    __syncthreads();
#pragma unroll
    for (int i = 0; i < 4; i++)
        xT[(((size_t)tt * BB + b) * NNE + n0 + ty8 + i * 8) * CIN + c0 + tx] =
            __float2bfloat16(t[tx][ty8 + i * 8]);
}

struct WC6 { const float* s[6]; };
__global__ __launch_bounds__(256) void conv_weights(WC6 w, __nv_bfloat16* __restrict__ dst,
                                                    float* __restrict__ Z)
{
    int idx = blockIdx.x * 256 + threadIdx.x;
    int t = idx >> 16, i = idx & 65535;
    dst[(size_t)t * 65536 + i] = __float2bfloat16(w.s[t][i]);
    if (idx < 2 * BB * NNE) Z[idx] = 0.f;
}

__global__ __launch_bounds__(256) void gnorm(
    const __nv_bfloat16* __restrict__ g, const float* __restrict__ Z,
    unsigned char* __restrict__ gn8)
{
    size_t idx = ((size_t)blockIdx.x * 256 + threadIdx.x) * 2;
    int n = (int)(idx % NNE);
    size_t sb = idx / ((size_t)NNE * MIDC);
    const float* zr = Z + sb * NNE;
    float v0 = __bfloat162float(g[idx])     * __frcp_rn(zr[n])     * 16384.f;
    float v1 = __bfloat162float(g[idx + 1]) * __frcp_rn(zr[n + 1]) * 16384.f;
    *reinterpret_cast<unsigned short*>(gn8 + idx) = pack_e4m3(v0, v1);
}

// ============================ tensor kernels ============================

// Merged input convs. grid (18, BB, 5): o<3 -> ft8 (fp8 out), o>=3 -> g (bf16 out).
__global__ __launch_bounds__(256, 2) void k_inconv(
    const __nv_bfloat16* __restrict__ xT, const __nv_bfloat16* __restrict__ Wc,
    const float* __restrict__ ba, const float* __restrict__ ga, const float* __restrict__ ta,
    const float* __restrict__ bv, const float* __restrict__ gv, const float* __restrict__ tv,
    const float* __restrict__ bgav, const float* __restrict__ bgah,
    unsigned char* __restrict__ ft, __nv_bfloat16* __restrict__ g)
{
    extern __shared__ char dsm[];
    __shared__ float sS[128], sC[128];
    int tid = threadIdx.x, lane = tid & 31, wid = tid >> 5;
    int wm = wid & 1, wn = wid >> 1;
    int nt = blockIdx.x, b = blockIdx.y, o = blockIdx.z;

    if (o < 3 && tid < 128) {
        const float* bias  = (o == 0) ? ba : bv;
        const float* gamma = (o == 0) ? ga : gv;
        const float* beta  = (o == 0) ? ta : tv;
        float s = gamma[tid] * rsqrtf(1.f + 1e-5f);
        sS[tid] = s; sC[tid] = bias[tid] * s + beta[tid];
    }

    const __nv_bfloat16* A;
    const __nv_bfloat16* B;
    if (o < 3) {
        A = xT + (((size_t)o * BB + b) * NNE + (size_t)nt * 128) * CIN;
        B = Wc + (size_t)((o == 0) ? 0 : 1) * 65536;
    } else {
        A = Wc + (size_t)(2 + (o - 3)) * 65536;
        B = xT + ((size_t)b * NNE + (size_t)nt * 128) * CIN;
    }

    float acc[4][4][4];
    u32 sA = (u32)__cvta_generic_to_shared(dsm);
    u32 sB = sA + NSTAGE * TILE_B;
    hmma_gemm(sA, sB, A, CIN, B, CIN, CIN, tid, acc);

    if (o < 3) {
        unsigned char* dst = ft + (size_t)o * (size_t)BB * NNE * MIDC
                                + ((size_t)b * NNE + (size_t)nt * 128) * MIDC;
        const bool even = ((lane & 1) == 0);
#pragma unroll
        for (int mf = 0; mf < 4; mf++)
#pragma unroll
            for (int nf = 0; nf < 4; nf++)
#pragma unroll
                for (int h = 0; h < 2; h++) {
                    int r = wm * 64 + mf * 16 + (lane >> 2) + h * 8;
                    int c = wn * 32 + nf * 8 + ((lane & 3) << 1);
                    float y0 = fmaxf(acc[mf][nf][h * 2]     * sS[c]     + sC[c],     0.f);
                    float y1 = fmaxf(acc[mf][nf][h * 2 + 1] * sS[c + 1] + sC[c + 1], 0.f);
                    u32 mine = (u32)pack_e4m3(y0, y1);
                    u32 other = __shfl_xor_sync(0xffffffffu, mine, 1);
                    if (even)
                        *reinterpret_cast<u32*>(dst + (size_t)r * MIDC + c) =
                            mine | (other << 16);
                }
    } else {
        const float* bias = (o == 3) ? bgav : bgah;
        __nv_bfloat16* dst = g + (size_t)((o - 3) * BB + b) * MIDC * NNE + (size_t)nt * 128;
#pragma unroll
        for (int mf = 0; mf < 4; mf++)
#pragma unroll
            for (int nf = 0; nf < 4; nf++)
#pragma unroll
                for (int h = 0; h < 2; h++) {
                    int r = wm * 64 + mf * 16 + (lane >> 2) + h * 8;
                    int c = wn * 32 + nf * 8 + ((lane & 3) << 1);
                    float bval = bias[r];
                    *reinterpret_cast<u32*>(dst + (size_t)r * NNE + c) =
                        pack_bf16(acc[mf][nf][h * 2] + bval, acc[mf][nf][h * 2 + 1] + bval);
                }
    }
}

// Pipelined score kernel: fixed j-tile, loop over all 18 i-tiles.
// fa_j resident in smem; fq streamed through 3-slot cp.async ring.
// ET8[sel][b][j][i] = e4m3(exp(scale*fa8[j]·fq8[i]) / 8); Z += col sums.
// grid (jt 18, b + 8*sel)
__global__ __launch_bounds__(256, 2) void k_score(
    const unsigned char* __restrict__ ft, unsigned char* __restrict__ et,
    float* __restrict__ Z)
{
    extern __shared__ char dsm[];
    __shared__ float zs[2][128];
    int tid = threadIdx.x, lane = tid & 31, wid = tid >> 5;
    int wm = wid & 1, wn = wid >> 1;
    int jt = blockIdx.x;
    int z = blockIdx.y, b = z & 7, sel = z >> 3;

    const char* fa = (const char*)ft + (size_t)b * NNE * MIDC + (size_t)jt * 128 * MIDC;
    const char* fq = (const char*)ft + (size_t)(1 + sel) * (size_t)BB * NNE * MIDC
                                     + (size_t)b * NNE * MIDC;

    u32 sA = (u32)__cvta_generic_to_shared(dsm);   // 16 KB resident fa_j
    u32 sB = sA + TILE_B;                          // 3 ring slots

    tile_load(sA, fa, MIDC, 0, tid);
    CP_COMMIT();                                   // group: A
    tile_load(sB, fq, MIDC, 0, tid);
    CP_COMMIT();                                   // group: B0
    tile_load(sB + TILE_B, fq + (size_t)128 * MIDC, MIDC, 0, tid);
    CP_COMMIT();                                   // group: B1

    unsigned char* dstBase = et + ((size_t)(sel * BB + b) * NNE + (size_t)jt * 128) * NNE;
    float* Zrow = Z + (size_t)(sel * BB + b) * NNE;
    const bool even = ((lane & 1) == 0);

    for (int it = 0; it < 18; it++) {
        asm volatile("cp.async.wait_group 1;" ::: "memory");  // B(it) (and A at it=0) ready
        __syncthreads();
        if (it + 2 < 18)
            tile_load(sB + ((it + 2) % 3) * TILE_B,
                      fq + (size_t)(it + 2) * 128 * MIDC, MIDC, 0, tid);
        CP_COMMIT();

        const u32 bbuf = sB + (it % 3) * TILE_B;
        float acc[4][4][4];
#pragma unroll
        for (int i = 0; i < 4; i++)
#pragma unroll
            for (int j = 0; j < 4; j++)
#pragma unroll
                for (int e = 0; e < 4; e++) acc[i][j][e] = 0.f;

#pragma unroll
        for (int k32 = 0; k32 < 4; k32++) {
            u32 a[4][4];
#pragma unroll
            for (int f = 0; f < 4; f++) {
                int row = wm * 64 + f * 16 + (lane & 15);
                int ch  = k32 * 2 + (lane >> 4);
                ldsm_x4(sA + sw64(row, ch), a[f][0], a[f][1], a[f][2], a[f][3]);
            }
            u32 bfr[4][2];
#pragma unroll
            for (int p = 0; p < 2; p++) {
                int row = wn * 32 + p * 16 + ((lane & 16) >> 1) + (lane & 7);
                int ch  = k32 * 2 + ((lane >> 3) & 1);
                ldsm_x4(bbuf + sw64(row, ch), bfr[2 * p][0], bfr[2 * p][1],
                        bfr[2 * p + 1][0], bfr[2 * p + 1][1]);
            }
#pragma unroll
            for (int mf = 0; mf < 4; mf++)
#pragma unroll
                for (int nf = 0; nf < 4; nf++)
                    mma16832_fp8(acc[mf][nf], a[mf], bfr[nf][0], bfr[nf][1]);
        }

        // epilogue: exp -> fp8 store -> Z column sums
#pragma unroll
        for (int mf = 0; mf < 4; mf++)
#pragma unroll
            for (int nf = 0; nf < 4; nf++)
#pragma unroll
                for (int e = 0; e < 4; e++)
                    acc[mf][nf][e] = __expf(acc[mf][nf][e] * SCALE_S);

        unsigned char* dst = dstBase + (size_t)it * 128;
#pragma unroll
        for (int mf = 0; mf < 4; mf++)
#pragma unroll
            for (int nf = 0; nf < 4; nf++)
#pragma unroll
                for (int h = 0; h < 2; h++) {
                    int r = wm * 64 + mf * 16 + (lane >> 2) + h * 8;
                    u32 mine = (u32)pack_e4m3(acc[mf][nf][h * 2] * SCALE_E,
                                              acc[mf][nf][h * 2 + 1] * SCALE_E);
                    u32 other = __shfl_xor_sync(0xffffffffu, mine, 1);
                    if (even) {
                        int c = wn * 32 + nf * 8 + ((lane & 3) << 1);
                        *reinterpret_cast<u32*>(dst + (size_t)r * NNE + c) =
                            mine | (other << 16);
                    }
                }

#pragma unroll
        for (int nf = 0; nf < 4; nf++) {
            float s0 = 0.f, s1 = 0.f;
#pragma unroll
            for (int mf = 0; mf < 4; mf++) {
                s0 += acc[mf][nf][0] + acc[mf][nf][2];
                s1 += acc[mf][nf][1] + acc[mf][nf][3];
            }
#pragma unroll
            for (int off = 4; off < 32; off <<= 1) {
                s0 += __shfl_xor_sync(0xffffffffu, s0, off);
                s1 += __shfl_xor_sync(0xffffffffu, s1, off);
            }
            if (lane < 4) {
                int c = wn * 32 + nf * 8 + lane * 2;
                zs[wm][c] = s0;
                zs[wm][c + 1] = s1;
            }
        }
        __syncthreads();
        if (tid < 128)
            atomicAdd(&Zrow[(size_t)it * 128 + tid], zs[0][tid] + zs[1][tid]);
        __syncthreads();   // protect zs before next iteration overwrites
    }
}

// oT[sel][b][j][m] = (1/2048) * sum_i ET8[j][i]·gn8[m][i]. grid (jt 18, 1, b+8*sel).
__global__ __launch_bounds__(256, 2) void k_ogemm(
    const unsigned char* __restrict__ et, const unsigned char* __restrict__ gn8,
    __nv_bfloat16* __restrict__ oT)
{
    extern __shared__ char dsm[];
    int tid = threadIdx.x, lane = tid & 31, wid = tid >> 5;
    int wm = wid & 1, wn = wid >> 1;
    int jt = blockIdx.x;
    int z = blockIdx.z, b = z & 7, sel = z >> 3;

    const char* A = (const char*)et + ((size_t)(sel * BB + b) * NNE + (size_t)jt * 128) * NNE;
    const char* B = (const char*)gn8 + (size_t)(sel * BB + b) * MIDC * NNE;

    float acc[4][4][4];
    u32 sA = (u32)__cvta_generic_to_shared(dsm);
    u32 sB = sA + NSTAGE * TILE_B;
    qmma_gemm(sA, sB, A, NNE, B, NNE, NNE, tid, acc);

    __nv_bfloat16* dst = oT + ((size_t)(sel * BB + b) * NNE + (size_t)jt * 128) * MIDC;
#pragma unroll
    for (int mf = 0; mf < 4; mf++)
#pragma unroll
        for (int nf = 0; nf < 4; nf++)
#pragma unroll
            for (int h = 0; h < 2; h++) {
                int r = wm * 64 + mf * 16 + (lane >> 2) + h * 8;
                int c = wn * 32 + nf * 8 + ((lane & 3) << 1);
                *reinterpret_cast<u32*>(dst + (size_t)r * MIDC + c) =
                    pack_bf16(acc[mf][nf][h * 2] * INV_OSCALE,
                              acc[mf][nf][h * 2 + 1] * INV_OSCALE);
            }
}

// out[sel][b][cout][n] = Wf·oT^T + bias + x. grid (nt 18, ct 4, b+8*sel).
__global__ __launch_bounds__(256, 2) void k_outconv(
    const __nv_bfloat16* __restrict__ Wc, const __nv_bfloat16* __restrict__ oT,
    const float* __restrict__ bfav, const float* __restrict__ bfah,
    const float* __restrict__ x,
    float* __restrict__ out_v, float* __restrict__ out_h)
{
    extern __shared__ char dsm[];
    int tid = threadIdx.x, lane = tid & 31, wid = tid >> 5;
    int wm = wid & 1, wn = wid >> 1;
    int nt = blockIdx.x, ct = blockIdx.y;
    int z = blockIdx.z, b = z & 7, sel = z >> 3;

    const __nv_bfloat16* A = Wc + (size_t)(4 + sel) * 65536 + (size_t)ct * 128 * MIDC;
    const __nv_bfloat16* B = oT + ((size_t)(sel * BB + b) * NNE + (size_t)nt * 128) * MIDC;

    float acc[4][4][4];
    u32 sA = (u32)__cvta_generic_to_shared(dsm);
    u32 sB = sA + NSTAGE * TILE_B;
    hmma_gemm(sA, sB, A, MIDC, B, MIDC, MIDC, tid, acc);

    const float* bias = (sel == 0) ? bfav : bfah;
    float* outp = (sel == 0) ? out_v : out_h;
#pragma unroll
    for (int mf = 0; mf < 4; mf++)
#pragma unroll
        for (int nf = 0; nf < 4; nf++)
#pragma unroll
            for (int h = 0; h < 2; h++) {
                int r = wm * 64 + mf * 16 + (lane >> 2) + h * 8;
                int c = wn * 32 + nf * 8 + ((lane & 3) << 1);
                int cout = ct * 128 + r;
                size_t base = ((size_t)b * CIN + cout) * NNE + (size_t)nt * 128 + c;
                float2 xv = *reinterpret_cast<const float2*>(x + base);
                float bval = bias[cout];
                *reinterpret_cast<float2*>(outp + base) =
                    make_float2(acc[mf][nf][h * 2] + bval + xv.x,
                                acc[mf][nf][h * 2 + 1] + bval + xv.y);
            }
}

// ============================================================================
extern "C" void kernel_launch(void* const* d_in, const int* in_sizes, int n_in,
                              void* d_out, int out_size)
{
    (void)in_sizes; (void)n_in; (void)out_size;

    const float* x    = (const float*)d_in[0];
    const float* x_h  = (const float*)d_in[1];
    const float* x_v  = (const float*)d_in[2];
    const float* Wa   = (const float*)d_in[3];
    const float* ba   = (const float*)d_in[4];
    const float* ga   = (const float*)d_in[5];
    const float* ta   = (const float*)d_in[6];
    const float* Wv   = (const float*)d_in[7];
    const float* bv   = (const float*)d_in[8];
    const float* gv   = (const float*)d_in[9];
    const float* tv   = (const float*)d_in[10];
    const float* Wgav = (const float*)d_in[11];
    const float* bgav = (const float*)d_in[12];
    const float* Wgah = (const float*)d_in[13];
    const float* bgah = (const float*)d_in[14];
    const float* Wfav = (const float*)d_in[15];
    const float* bfav = (const float*)d_in[16];
    const float* Wfah = (const float*)d_in[17];
    const float* bfah = (const float*)d_in[18];

    void* sp = nullptr;
    cudaGetSymbolAddress(&sp, d_scratch);
    char* base = (char*)sp;
    __nv_bfloat16* xT  = (__nv_bfloat16*)(base + XT_OFF);
    unsigned char* ft  = (unsigned char*)(base + FT_OFF);
    __nv_bfloat16* g   = (__nv_bfloat16*)(base + G_OFF);
    unsigned char* gn8 = (unsigned char*)(base + GN_OFF);
    unsigned char* et  = (unsigned char*)(base + ET_OFF);
    float*         Zp  = (float*)(base + Z_OFF);
    __nv_bfloat16* oT  = (__nv_bfloat16*)(base + OT_OFF);
    __nv_bfloat16* Wc  = (__nv_bfloat16*)(base + WC_OFF);

    float* out_h = (float*)d_out;
    float* out_v = out_h + (size_t)BB * CIN * NNE;

    static int attr_done = 0;
    if (!attr_done) {
        cudaFuncSetAttribute(k_inconv,  cudaFuncAttributeMaxDynamicSharedMemorySize, SMEM_DYN);
        cudaFuncSetAttribute(k_score,   cudaFuncAttributeMaxDynamicSharedMemorySize, SMEM_SCORE);
        cudaFuncSetAttribute(k_ogemm,   cudaFuncAttributeMaxDynamicSharedMemorySize, SMEM_DYN);
        cudaFuncSetAttribute(k_outconv, cudaFuncAttributeMaxDynamicSharedMemorySize, SMEM_DYN);
        attr_done = 1;
    }

    // prep: transpose x to bf16 [n][c]; weights to bf16; zero Z
    transpose_x<<<dim3(NNE / 32, CIN / 32, 3 * BB), 256>>>(x, x_v, x_h, xT);
    WC6 w = {{ Wa, Wv, Wgav, Wgah, Wfav, Wfah }};
    conv_weights<<<1536, 256>>>(w, Wc, Zp);

    // all 5 input convs in one launch: f -> fp8, g -> bf16
    k_inconv<<<dim3(18, BB, 5), 256, SMEM_DYN>>>(xT, Wc, ba, ga, ta, bv, gv, tv,
                                                 bgav, bgah, ft, g);

    // scores: pipelined FP8 GEMM over i-tiles; ET8 + Z
    k_score<<<dim3(18, 16), 256, SMEM_SCORE>>>(ft, et, Zp);

    // fold 16384/Z into g -> e4m3
    gnorm<<<(2 * BB * MIDC * NNE) / 512, 256>>>(g, Zp, gn8);

    // oT = (ET8 · gn8^T) / 2048  — FP8 tensor GEMM
    k_ogemm<<<dim3(18, 1, 16), 256, SMEM_DYN>>>(et, gn8, oT);

    // output convs + residual
    k_outconv<<<dim3(18, 4, 16), 256, SMEM_DYN>>>(Wc, oT, bfav, bfah, x, out_v, out_h);
}

// round 15
// speedup vs baseline: 1.0042x; 1.0042x over previous
#include <cuda_runtime.h>
#include <cuda_bf16.h>
#include <cstdint>

typedef unsigned int u32;
typedef unsigned long long u64;

#define BB   8
#define CIN  512
#define MIDC 128
#define NNE  2304
// exp(scale*S)/8 = exp2( S * (scale*log2e) - 3 )
#define C2FOLD 0.12751876698699227f   // SCALE_S * log2(e)
#define INV_OSCALE (1.0f/2048.0f)

// ---------------- scratch layout (bytes) ----------------
#define XT_SZ   ((size_t)3*BB*NNE*CIN*2)
#define FT_ONE  ((size_t)BB*NNE*MIDC)       // fp8
#define G_SZ    ((size_t)2*BB*MIDC*NNE*2)   // bf16
#define GN_SZ   ((size_t)2*BB*MIDC*NNE)     // fp8
#define ET_SZ   ((size_t)2*BB*NNE*NNE)      // fp8
#define Z_SZ    ((size_t)2*BB*NNE*4)
#define OT_SZ   ((size_t)2*BB*NNE*MIDC*2)
#define WC_SZ   ((size_t)6*65536*2)

#define XT_OFF  0ull
#define FT_OFF  (XT_OFF + XT_SZ)
#define G_OFF   (FT_OFF + 3*FT_ONE)
#define GN_OFF  (G_OFF + G_SZ)
#define ET_OFF  (GN_OFF + GN_SZ)
#define Z_OFF   (ET_OFF + ET_SZ)
#define OT_OFF  (Z_OFF + Z_SZ)
#define WC_OFF  (OT_OFF + OT_SZ)
#define TOTAL_SCRATCH (WC_OFF + WC_SZ)

__device__ __align__(1024) char d_scratch[TOTAL_SCRATCH];

// ---------------- MMA building blocks ----------------
__device__ __forceinline__ u32 pack_bf16(float lo, float hi) {
    u32 r; asm("cvt.rn.bf16x2.f32 %0, %1, %2;" : "=r"(r) : "f"(hi), "f"(lo)); return r;
}
__device__ __forceinline__ unsigned short pack_e4m3(float lo, float hi) {
    unsigned short r;
    asm("cvt.rn.satfinite.e4m3x2.f32 %0, %1, %2;" : "=h"(r) : "f"(hi), "f"(lo));
    return r;
}
__device__ __forceinline__ float ex2(float x) {
    float r; asm("ex2.approx.f32 %0, %1;" : "=f"(r) : "f"(x)); return r;
}
__device__ __forceinline__ void cpasync16(u32 saddr, const void* g) {
    asm volatile("cp.async.cg.shared.global [%0], [%1], 16;" :: "r"(saddr), "l"(g));
}
#define CP_COMMIT() asm volatile("cp.async.commit_group;" ::: "memory")

__device__ __forceinline__ void ldsm_x4(u32 a, u32& r0, u32& r1, u32& r2, u32& r3) {
    asm volatile("ldmatrix.sync.aligned.m8n8.x4.shared.b16 {%0,%1,%2,%3}, [%4];"
                 : "=r"(r0), "=r"(r1), "=r"(r2), "=r"(r3) : "r"(a));
}
__device__ __forceinline__ void mma16816(float c[4], const u32 a[4], u32 b0, u32 b1) {
    asm volatile("mma.sync.aligned.m16n8k16.row.col.f32.bf16.bf16.f32 "
                 "{%0,%1,%2,%3}, {%4,%5,%6,%7}, {%8,%9}, {%0,%1,%2,%3};"
                 : "+f"(c[0]), "+f"(c[1]), "+f"(c[2]), "+f"(c[3])
                 : "r"(a[0]), "r"(a[1]), "r"(a[2]), "r"(a[3]), "r"(b0), "r"(b1));
}
__device__ __forceinline__ void mma16832_fp8(float c[4], const u32 a[4], u32 b0, u32 b1) {
    asm volatile("mma.sync.aligned.m16n8k32.row.col.f32.e4m3.e4m3.f32 "
                 "{%0,%1,%2,%3}, {%4,%5,%6,%7}, {%8,%9}, {%0,%1,%2,%3};"
                 : "+f"(c[0]), "+f"(c[1]), "+f"(c[2]), "+f"(c[3])
                 : "r"(a[0]), "r"(a[1]), "r"(a[2]), "r"(a[3]), "r"(b0), "r"(b1));
}

// Tile: 128 rows x 128 B. 8 x 16B chunks/row. Swizzle cc = c ^ (r&7).
#define TILE_B 16384
#define NSTAGE 3

__device__ __forceinline__ u32 sw64(int r, int ch) {
    return (u32)(r * 128 + ((ch ^ (r & 7)) << 4));
}

__device__ __forceinline__ void tile_load(u32 sdst, const char* src,
                                          size_t pitchB, int k0B, int tid) {
    int r = tid >> 1;
    const char* g = src + (size_t)r * pitchB + k0B;
#pragma unroll
    for (int i = 0; i < 4; i++) {
        int c = (tid & 1) * 4 + i;
        cpasync16(sdst + sw64(r, c), g + c * 16);
    }
}

// CTA 128x128 bf16 GEMM
__device__ __forceinline__ void hmma_gemm(
    u32 sA, u32 sB,
    const __nv_bfloat16* __restrict__ A, size_t pA,
    const __nv_bfloat16* __restrict__ B, size_t pB,
    int Kd, int tid, float acc[4][4][4])
{
#pragma unroll
    for (int i = 0; i < 4; i++)
#pragma unroll
        for (int j = 0; j < 4; j++)
#pragma unroll
            for (int e = 0; e < 4; e++) acc[i][j][e] = 0.f;

    const int lane = tid & 31, wid = tid >> 5;
    const int wm = wid & 1, wn = wid >> 1;
    const int T = Kd / 64;
    const char* Ab = (const char*)A;
    const char* Bb = (const char*)B;
    const size_t pAB = pA * 2, pBB = pB * 2;

    tile_load(sA, Ab, pAB, 0, tid);
    tile_load(sB, Bb, pBB, 0, tid);
    CP_COMMIT();
    if (T > 1) {
        tile_load(sA + TILE_B, Ab, pAB, 128, tid);
        tile_load(sB + TILE_B, Bb, pBB, 128, tid);
    }
    CP_COMMIT();

    int slot_next = 2 % NSTAGE;
    for (int t = 0; t < T; t++) {
        asm volatile("cp.async.wait_group 1;" ::: "memory");
        __syncthreads();
        if (t + 2 < T) {
            tile_load(sA + slot_next * TILE_B, Ab, pAB, (t + 2) * 128, tid);
            tile_load(sB + slot_next * TILE_B, Bb, pBB, (t + 2) * 128, tid);
        }
        CP_COMMIT();
        slot_next = (slot_next + 1 == NSTAGE) ? 0 : slot_next + 1;

        const int cur = t % NSTAGE;
        const u32 abuf = sA + cur * TILE_B;
        const u32 bbuf = sB + cur * TILE_B;
#pragma unroll
        for (int k16 = 0; k16 < 4; k16++) {
            u32 a[4][4];
#pragma unroll
            for (int f = 0; f < 4; f++) {
                int row = wm * 64 + f * 16 + (lane & 15);
                int ch  = k16 * 2 + (lane >> 4);
                ldsm_x4(abuf + sw64(row, ch), a[f][0], a[f][1], a[f][2], a[f][3]);
            }
            u32 b[4][2];
#pragma unroll
            for (int p = 0; p < 2; p++) {
                int row = wn * 32 + p * 16 + ((lane & 16) >> 1) + (lane & 7);
                int ch  = k16 * 2 + ((lane >> 3) & 1);
                ldsm_x4(bbuf + sw64(row, ch), b[2 * p][0], b[2 * p][1],
                        b[2 * p + 1][0], b[2 * p + 1][1]);
            }
#pragma unroll
            for (int mf = 0; mf < 4; mf++)
#pragma unroll
                for (int nf = 0; nf < 4; nf++)
                    mma16816(acc[mf][nf], a[mf], b[nf][0], b[nf][1]);
        }
    }
}

// CTA 128x128 FP8 GEMM (streamed K)
__device__ __forceinline__ void qmma_gemm(
    u32 sA, u32 sB,
    const char* __restrict__ A, size_t pAB,
    const char* __restrict__ B, size_t pBB,
    int KdB, int tid, float acc[4][4][4])
{
#pragma unroll
    for (int i = 0; i < 4; i++)
#pragma unroll
        for (int j = 0; j < 4; j++)
#pragma unroll
            for (int e = 0; e < 4; e++) acc[i][j][e] = 0.f;

    const int lane = tid & 31, wid = tid >> 5;
    const int wm = wid & 1, wn = wid >> 1;
    const int T = KdB / 128;

    tile_load(sA, A, pAB, 0, tid);
    tile_load(sB, B, pBB, 0, tid);
    CP_COMMIT();
    if (T > 1) {
        tile_load(sA + TILE_B, A, pAB, 128, tid);
        tile_load(sB + TILE_B, B, pBB, 128, tid);
    }
    CP_COMMIT();

    int slot_next = 2 % NSTAGE;
    for (int t = 0; t < T; t++) {
        asm volatile("cp.async.wait_group 1;" ::: "memory");
        __syncthreads();
        if (t + 2 < T) {
            tile_load(sA + slot_next * TILE_B, A, pAB, (t + 2) * 128, tid);
            tile_load(sB + slot_next * TILE_B, B, pBB, (t + 2) * 128, tid);
        }
        CP_COMMIT();
        slot_next = (slot_next + 1 == NSTAGE) ? 0 : slot_next + 1;

        const int cur = t % NSTAGE;
        const u32 abuf = sA + cur * TILE_B;
        const u32 bbuf = sB + cur * TILE_B;
#pragma unroll
        for (int k32 = 0; k32 < 4; k32++) {
            u32 a[4][4];
#pragma unroll
            for (int f = 0; f < 4; f++) {
                int row = wm * 64 + f * 16 + (lane & 15);
                int ch  = k32 * 2 + (lane >> 4);
                ldsm_x4(abuf + sw64(row, ch), a[f][0], a[f][1], a[f][2], a[f][3]);
            }
            u32 b[4][2];
#pragma unroll
            for (int p = 0; p < 2; p++) {
                int row = wn * 32 + p * 16 + ((lane & 16) >> 1) + (lane & 7);
                int ch  = k32 * 2 + ((lane >> 3) & 1);
                ldsm_x4(bbuf + sw64(row, ch), b[2 * p][0], b[2 * p][1],
                        b[2 * p + 1][0], b[2 * p + 1][1]);
            }
#pragma unroll
            for (int mf = 0; mf < 4; mf++)
#pragma unroll
                for (int nf = 0; nf < 4; nf++)
                    mma16832_fp8(acc[mf][nf], a[mf], b[nf][0], b[nf][1]);
        }
    }
}

#define SMEM_DYN   (2 * NSTAGE * TILE_B)   // 96 KB
#define SMEM_SCORE (4 * TILE_B)            // 64 KB: A + 3 B slots

// ============================ SIMT prep ============================
__global__ __launch_bounds__(256) void transpose_x(
    const float* __restrict__ x, const float* __restrict__ x_v,
    const float* __restrict__ x_h, __nv_bfloat16* __restrict__ xT)
{
    __shared__ float t[32][33];
    int z = blockIdx.z, tt = z >> 3, b = z & 7;
    const float* src = (tt == 0) ? x : (tt == 1 ? x_v : x_h);
    int n0 = blockIdx.x * 32, c0 = blockIdx.y * 32;
    int tx = threadIdx.x & 31, ty8 = threadIdx.x >> 5;
#pragma unroll
    for (int i = 0; i < 4; i++)
        t[ty8 + i * 8][tx] = src[((size_t)b * CIN + c0 + ty8 + i * 8) * NNE + n0 + tx];
    __syncthreads();
#pragma unroll
    for (int i = 0; i < 4; i++)
        xT[(((size_t)tt * BB + b) * NNE + n0 + ty8 + i * 8) * CIN + c0 + tx] =
            __float2bfloat16(t[tx][ty8 + i * 8]);
}

struct WC6 { const float* s[6]; };
__global__ __launch_bounds__(256) void conv_weights(WC6 w, __nv_bfloat16* __restrict__ dst,
                                                    float* __restrict__ Z)
{
    int idx = blockIdx.x * 256 + threadIdx.x;
    int t = idx >> 16, i = idx & 65535;
    dst[(size_t)t * 65536 + i] = __float2bfloat16(w.s[t][i]);
    if (idx < 2 * BB * NNE) Z[idx] = 0.f;
}

// gn8 = e4m3(g * 2048 / Z8)   (Z8 = sum of E/8)
__global__ __launch_bounds__(256) void gnorm(
    const __nv_bfloat16* __restrict__ g, const float* __restrict__ Z,
    unsigned char* __restrict__ gn8)
{
    size_t idx = ((size_t)blockIdx.x * 256 + threadIdx.x) * 2;
    int n = (int)(idx % NNE);
    size_t sb = idx / ((size_t)NNE * MIDC);
    const float* zr = Z + sb * NNE;
    float v0 = __bfloat162float(g[idx])     * __frcp_rn(zr[n])     * 2048.f;
    float v1 = __bfloat162float(g[idx + 1]) * __frcp_rn(zr[n + 1]) * 2048.f;
    *reinterpret_cast<unsigned short*>(gn8 + idx) = pack_e4m3(v0, v1);
}

// ============================ tensor kernels ============================

// Merged input convs. grid (18, BB, 5): o<3 -> ft8 (fp8 out), o>=3 -> g (bf16 out).
__global__ __launch_bounds__(256, 2) void k_inconv(
    const __nv_bfloat16* __restrict__ xT, const __nv_bfloat16* __restrict__ Wc,
    const float* __restrict__ ba, const float* __restrict__ ga, const float* __restrict__ ta,
    const float* __restrict__ bv, const float* __restrict__ gv, const float* __restrict__ tv,
    const float* __restrict__ bgav, const float* __restrict__ bgah,
    unsigned char* __restrict__ ft, __nv_bfloat16* __restrict__ g)
{
    extern __shared__ char dsm[];
    __shared__ float sS[128], sC[128];
    int tid = threadIdx.x, lane = tid & 31, wid = tid >> 5;
    int wm = wid & 1, wn = wid >> 1;
    int nt = blockIdx.x, b = blockIdx.y, o = blockIdx.z;

    if (o < 3 && tid < 128) {
        const float* bias  = (o == 0) ? ba : bv;
        const float* gamma = (o == 0) ? ga : gv;
        const float* beta  = (o == 0) ? ta : tv;
        float s = gamma[tid] * rsqrtf(1.f + 1e-5f);
        sS[tid] = s; sC[tid] = bias[tid] * s + beta[tid];
    }

    const __nv_bfloat16* A;
    const __nv_bfloat16* B;
    if (o < 3) {
        A = xT + (((size_t)o * BB + b) * NNE + (size_t)nt * 128) * CIN;
        B = Wc + (size_t)((o == 0) ? 0 : 1) * 65536;
    } else {
        A = Wc + (size_t)(2 + (o - 3)) * 65536;
        B = xT + ((size_t)b * NNE + (size_t)nt * 128) * CIN;
    }

    float acc[4][4][4];
    u32 sA = (u32)__cvta_generic_to_shared(dsm);
    u32 sB = sA + NSTAGE * TILE_B;
    hmma_gemm(sA, sB, A, CIN, B, CIN, CIN, tid, acc);

    if (o < 3) {
        unsigned char* dst = ft + (size_t)o * (size_t)BB * NNE * MIDC
                                + ((size_t)b * NNE + (size_t)nt * 128) * MIDC;
        const bool even = ((lane & 1) == 0);
#pragma unroll
        for (int mf = 0; mf < 4; mf++)
#pragma unroll
            for (int nf = 0; nf < 4; nf++)
#pragma unroll
                for (int h = 0; h < 2; h++) {
                    int r = wm * 64 + mf * 16 + (lane >> 2) + h * 8;
                    int c = wn * 32 + nf * 8 + ((lane & 3) << 1);
                    float y0 = fmaxf(acc[mf][nf][h * 2]     * sS[c]     + sC[c],     0.f);
                    float y1 = fmaxf(acc[mf][nf][h * 2 + 1] * sS[c + 1] + sC[c + 1], 0.f);
                    u32 mine = (u32)pack_e4m3(y0, y1);
                    u32 other = __shfl_xor_sync(0xffffffffu, mine, 1);
                    if (even)
                        *reinterpret_cast<u32*>(dst + (size_t)r * MIDC + c) =
                            mine | (other << 16);
                }
    } else {
        const float* bias = (o == 3) ? bgav : bgah;
        __nv_bfloat16* dst = g + (size_t)((o - 3) * BB + b) * MIDC * NNE + (size_t)nt * 128;
#pragma unroll
        for (int mf = 0; mf < 4; mf++)
#pragma unroll
            for (int nf = 0; nf < 4; nf++)
#pragma unroll
                for (int h = 0; h < 2; h++) {
                    int r = wm * 64 + mf * 16 + (lane >> 2) + h * 8;
                    int c = wn * 32 + nf * 8 + ((lane & 3) << 1);
                    float bval = bias[r];
                    *reinterpret_cast<u32*>(dst + (size_t)r * NNE + c) =
                        pack_bf16(acc[mf][nf][h * 2] + bval, acc[mf][nf][h * 2 + 1] + bval);
                }
    }
}

// Pipelined score kernel. ET8 = exp2(S*C2FOLD - 3) (= exp(scale*S)/8);
// Z8 += column sums of stored values. grid (jt 18, b + 8*sel)
__global__ __launch_bounds__(256, 2) void k_score(
    const unsigned char* __restrict__ ft, unsigned char* __restrict__ et,
    float* __restrict__ Z)
{
    extern __shared__ char dsm[];
    __shared__ float zs[2][2][128];   // [buf][wm][c]
    int tid = threadIdx.x, lane = tid & 31, wid = tid >> 5;
    int wm = wid & 1, wn = wid >> 1;
    int jt = blockIdx.x;
    int z = blockIdx.y, b = z & 7, sel = z >> 3;

    const char* fa = (const char*)ft + (size_t)b * NNE * MIDC + (size_t)jt * 128 * MIDC;
    const char* fq = (const char*)ft + (size_t)(1 + sel) * (size_t)BB * NNE * MIDC
                                     + (size_t)b * NNE * MIDC;

    u32 sA = (u32)__cvta_generic_to_shared(dsm);
    u32 sB = sA + TILE_B;

    tile_load(sA, fa, MIDC, 0, tid);
    CP_COMMIT();
    tile_load(sB, fq, MIDC, 0, tid);
    CP_COMMIT();
    tile_load(sB + TILE_B, fq + (size_t)128 * MIDC, MIDC, 0, tid);
    CP_COMMIT();

    unsigned char* dstBase = et + ((size_t)(sel * BB + b) * NNE + (size_t)jt * 128) * NNE;
    float* Zrow = Z + (size_t)(sel * BB + b) * NNE;
    const bool even = ((lane & 1) == 0);

    for (int it = 0; it < 18; it++) {
        asm volatile("cp.async.wait_group 1;" ::: "memory");
        __syncthreads();
        if (it + 2 < 18)
            tile_load(sB + ((it + 2) % 3) * TILE_B,
                      fq + (size_t)(it + 2) * 128 * MIDC, MIDC, 0, tid);
        CP_COMMIT();

        const u32 bbuf = sB + (it % 3) * TILE_B;
        float acc[4][4][4];
#pragma unroll
        for (int i = 0; i < 4; i++)
#pragma unroll
            for (int j = 0; j < 4; j++)
#pragma unroll
                for (int e = 0; e < 4; e++) acc[i][j][e] = 0.f;

#pragma unroll
        for (int k32 = 0; k32 < 4; k32++) {
            u32 a[4][4];
#pragma unroll
            for (int f = 0; f < 4; f++) {
                int row = wm * 64 + f * 16 + (lane & 15);
                int ch  = k32 * 2 + (lane >> 4);
                ldsm_x4(sA + sw64(row, ch), a[f][0], a[f][1], a[f][2], a[f][3]);
            }
            u32 bfr[4][2];
#pragma unroll
            for (int p = 0; p < 2; p++) {
                int row = wn * 32 + p * 16 + ((lane & 16) >> 1) + (lane & 7);
                int ch  = k32 * 2 + ((lane >> 3) & 1);
                ldsm_x4(bbuf + sw64(row, ch), bfr[2 * p][0], bfr[2 * p][1],
                        bfr[2 * p + 1][0], bfr[2 * p + 1][1]);
            }
#pragma unroll
            for (int mf = 0; mf < 4; mf++)
#pragma unroll
                for (int nf = 0; nf < 4; nf++)
                    mma16832_fp8(acc[mf][nf], a[mf], bfr[nf][0], bfr[nf][1]);
        }

        // epilogue: fused exp2 -> fp8 store -> Z8 column sums
#pragma unroll
        for (int mf = 0; mf < 4; mf++)
#pragma unroll
            for (int nf = 0; nf < 4; nf++)
#pragma unroll
                for (int e = 0; e < 4; e++)
                    acc[mf][nf][e] = ex2(fmaf(acc[mf][nf][e], C2FOLD, -3.0f));

        unsigned char* dst = dstBase + (size_t)it * 128;
#pragma unroll
        for (int mf = 0; mf < 4; mf++)
#pragma unroll
            for (int nf = 0; nf < 4; nf++)
#pragma unroll
                for (int h = 0; h < 2; h++) {
                    int r = wm * 64 + mf * 16 + (lane >> 2) + h * 8;
                    u32 mine = (u32)pack_e4m3(acc[mf][nf][h * 2],
                                              acc[mf][nf][h * 2 + 1]);
                    u32 other = __shfl_xor_sync(0xffffffffu, mine, 1);
                    if (even) {
                        int c = wn * 32 + nf * 8 + ((lane & 3) << 1);
                        *reinterpret_cast<u32*>(dst + (size_t)r * NNE + c) =
                            mine | (other << 16);
                    }
                }

        const int zb = it & 1;
#pragma unroll
        for (int nf = 0; nf < 4; nf++) {
            float s0 = 0.f, s1 = 0.f;
#pragma unroll
            for (int mf = 0; mf < 4; mf++) {
                s0 += acc[mf][nf][0] + acc[mf][nf][2];
                s1 += acc[mf][nf][1] + acc[mf][nf][3];
            }
#pragma unroll
            for (int off = 4; off < 32; off <<= 1) {
                s0 += __shfl_xor_sync(0xffffffffu, s0, off);
                s1 += __shfl_xor_sync(0xffffffffu, s1, off);
            }
            if (lane < 4) {
                int c = wn * 32 + nf * 8 + lane * 2;
                zs[zb][wm][c] = s0;
                zs[zb][wm][c + 1] = s1;
            }
        }
        __syncthreads();
        if (tid < 128)
            atomicAdd(&Zrow[(size_t)it * 128 + tid], zs[zb][0][tid] + zs[zb][1][tid]);
        // no trailing sync: next iteration writes the other zs buffer
    }
}

// oT[sel][b][j][m] = (1/2048) * sum_i ET8[j][i]·gn8[m][i]. grid (jt 18, 1, b+8*sel).
__global__ __launch_bounds__(256, 2) void k_ogemm(
    const unsigned char* __restrict__ et, const unsigned char* __restrict__ gn8,
    __nv_bfloat16* __restrict__ oT)
{
    extern __shared__ char dsm[];
    int tid = threadIdx.x, lane = tid & 31, wid = tid >> 5;
    int wm = wid & 1, wn = wid >> 1;
    int jt = blockIdx.x;
    int z = blockIdx.z, b = z & 7, sel = z >> 3;

    const char* A = (const char*)et + ((size_t)(sel * BB + b) * NNE + (size_t)jt * 128) * NNE;
    const char* B = (const char*)gn8 + (size_t)(sel * BB + b) * MIDC * NNE;

    float acc[4][4][4];
    u32 sA = (u32)__cvta_generic_to_shared(dsm);
    u32 sB = sA + NSTAGE * TILE_B;
    qmma_gemm(sA, sB, A, NNE, B, NNE, NNE, tid, acc);

    __nv_bfloat16* dst = oT + ((size_t)(sel * BB + b) * NNE + (size_t)jt * 128) * MIDC;
#pragma unroll
    for (int mf = 0; mf < 4; mf++)
#pragma unroll
        for (int nf = 0; nf < 4; nf++)
#pragma unroll
            for (int h = 0; h < 2; h++) {
                int r = wm * 64 + mf * 16 + (lane >> 2) + h * 8;
                int c = wn * 32 + nf * 8 + ((lane & 3) << 1);
                *reinterpret_cast<u32*>(dst + (size_t)r * MIDC + c) =
                    pack_bf16(acc[mf][nf][h * 2] * INV_OSCALE,
                              acc[mf][nf][h * 2 + 1] * INV_OSCALE);
            }
}

// out[sel][b][cout][n] = Wf·oT^T + bias + x. grid (nt 18, ct 4, b+8*sel).
__global__ __launch_bounds__(256, 2) void k_outconv(
    const __nv_bfloat16* __restrict__ Wc, const __nv_bfloat16* __restrict__ oT,
    const float* __restrict__ bfav, const float* __restrict__ bfah,
    const float* __restrict__ x,
    float* __restrict__ out_v, float* __restrict__ out_h)
{
    extern __shared__ char dsm[];
    int tid = threadIdx.x, lane = tid & 31, wid = tid >> 5;
    int wm = wid & 1, wn = wid >> 1;
    int nt = blockIdx.x, ct = blockIdx.y;
    int z = blockIdx.z, b = z & 7, sel = z >> 3;

    const __nv_bfloat16* A = Wc + (size_t)(4 + sel) * 65536 + (size_t)ct * 128 * MIDC;
    const __nv_bfloat16* B = oT + ((size_t)(sel * BB + b) * NNE + (size_t)nt * 128) * MIDC;

    float acc[4][4][4];
    u32 sA = (u32)__cvta_generic_to_shared(dsm);
    u32 sB = sA + NSTAGE * TILE_B;
    hmma_gemm(sA, sB, A, MIDC, B, MIDC, MIDC, tid, acc);

    const float* bias = (sel == 0) ? bfav : bfah;
    float* outp = (sel == 0) ? out_v : out_h;
#pragma unroll
    for (int mf = 0; mf < 4; mf++)
#pragma unroll
        for (int nf = 0; nf < 4; nf++)
#pragma unroll
            for (int h = 0; h < 2; h++) {
                int r = wm * 64 + mf * 16 + (lane >> 2) + h * 8;
                int c = wn * 32 + nf * 8 + ((lane & 3) << 1);
                int cout = ct * 128 + r;
                size_t base = ((size_t)b * CIN + cout) * NNE + (size_t)nt * 128 + c;
                float2 xv = *reinterpret_cast<const float2*>(x + base);
                float bval = bias[cout];
                *reinterpret_cast<float2*>(outp + base) =
                    make_float2(acc[mf][nf][h * 2] + bval + xv.x,
                                acc[mf][nf][h * 2 + 1] + bval + xv.y);
            }
}

// ============================================================================
extern "C" void kernel_launch(void* const* d_in, const int* in_sizes, int n_in,
                              void* d_out, int out_size)
{
    (void)in_sizes; (void)n_in; (void)out_size;

    const float* x    = (const float*)d_in[0];
    const float* x_h  = (const float*)d_in[1];
    const float* x_v  = (const float*)d_in[2];
    const float* Wa   = (const float*)d_in[3];
    const float* ba   = (const float*)d_in[4];
    const float* ga   = (const float*)d_in[5];
    const float* ta   = (const float*)d_in[6];
    const float* Wv   = (const float*)d_in[7];
    const float* bv   = (const float*)d_in[8];
    const float* gv   = (const float*)d_in[9];
    const float* tv   = (const float*)d_in[10];
    const float* Wgav = (const float*)d_in[11];
    const float* bgav = (const float*)d_in[12];
    const float* Wgah = (const float*)d_in[13];
    const float* bgah = (const float*)d_in[14];
    const float* Wfav = (const float*)d_in[15];
    const float* bfav = (const float*)d_in[16];
    const float* Wfah = (const float*)d_in[17];
    const float* bfah = (const float*)d_in[18];

    void* sp = nullptr;
    cudaGetSymbolAddress(&sp, d_scratch);
    char* base = (char*)sp;
    __nv_bfloat16* xT  = (__nv_bfloat16*)(base + XT_OFF);
    unsigned char* ft  = (unsigned char*)(base + FT_OFF);
    __nv_bfloat16* g   = (__nv_bfloat16*)(base + G_OFF);
    unsigned char* gn8 = (unsigned char*)(base + GN_OFF);
    unsigned char* et  = (unsigned char*)(base + ET_OFF);
    float*         Zp  = (float*)(base + Z_OFF);
    __nv_bfloat16* oT  = (__nv_bfloat16*)(base + OT_OFF);
    __nv_bfloat16* Wc  = (__nv_bfloat16*)(base + WC_OFF);

    float* out_h = (float*)d_out;
    float* out_v = out_h + (size_t)BB * CIN * NNE;

    static int attr_done = 0;
    if (!attr_done) {
        cudaFuncSetAttribute(k_inconv,  cudaFuncAttributeMaxDynamicSharedMemorySize, SMEM_DYN);
        cudaFuncSetAttribute(k_score,   cudaFuncAttributeMaxDynamicSharedMemorySize, SMEM_SCORE);
        cudaFuncSetAttribute(k_ogemm,   cudaFuncAttributeMaxDynamicSharedMemorySize, SMEM_DYN);
        cudaFuncSetAttribute(k_outconv, cudaFuncAttributeMaxDynamicSharedMemorySize, SMEM_DYN);
        attr_done = 1;
    }

    // prep
    transpose_x<<<dim3(NNE / 32, CIN / 32, 3 * BB), 256>>>(x, x_v, x_h, xT);
    WC6 w = {{ Wa, Wv, Wgav, Wgah, Wfav, Wfah }};
    conv_weights<<<1536, 256>>>(w, Wc, Zp);

    // all 5 input convs in one launch
    k_inconv<<<dim3(18, BB, 5), 256, SMEM_DYN>>>(xT, Wc, ba, ga, ta, bv, gv, tv,
                                                 bgav, bgah, ft, g);

    // scores: pipelined FP8 GEMM with fused exp2 epilogue
    k_score<<<dim3(18, 16), 256, SMEM_SCORE>>>(ft, et, Zp);

    // fold 2048/Z8 into g -> e4m3
    gnorm<<<(2 * BB * MIDC * NNE) / 512, 256>>>(g, Zp, gn8);

    // oT = (ET8 · gn8^T) / 2048
    k_ogemm<<<dim3(18, 1, 16), 256, SMEM_DYN>>>(et, gn8, oT);

    // output convs + residual
    k_outconv<<<dim3(18, 4, 16), 256, SMEM_DYN>>>(Wc, oT, bfav, bfah, x, out_v, out_h);
}

// round 16
// speedup vs baseline: 1.1104x; 1.1058x over previous
#include <cuda_runtime.h>
#include <cuda_bf16.h>
#include <cstdint>

typedef unsigned int u32;
typedef unsigned long long u64;

#define BB   8
#define CIN  512
#define MIDC 128
#define NNE  2304
// exp(scale*S)/8 = exp2( S * (scale*log2e) - 3 )
#define C2FOLD 0.12751876698699227f   // SCALE_S * log2(e)
#define INV_OSCALE (1.0f/2048.0f)

// ---------------- scratch layout (bytes) ----------------
#define XT_SZ   ((size_t)3*BB*NNE*CIN*2)
#define FT_ONE  ((size_t)BB*NNE*MIDC)       // fp8
#define G_SZ    ((size_t)2*BB*MIDC*NNE*2)   // bf16
#define GN_SZ   ((size_t)2*BB*MIDC*NNE)     // fp8
#define ET_SZ   ((size_t)2*BB*NNE*NNE)      // fp8
#define Z_SZ    ((size_t)2*BB*NNE*4)
#define OT_SZ   ((size_t)2*BB*NNE*MIDC*2)
#define WC_SZ   ((size_t)6*65536*2)

#define XT_OFF  0ull
#define FT_OFF  (XT_OFF + XT_SZ)
#define G_OFF   (FT_OFF + 3*FT_ONE)
#define GN_OFF  (G_OFF + G_SZ)
#define ET_OFF  (GN_OFF + GN_SZ)
#define Z_OFF   (ET_OFF + ET_SZ)
#define OT_OFF  (Z_OFF + Z_SZ)
#define WC_OFF  (OT_OFF + OT_SZ)
#define TOTAL_SCRATCH (WC_OFF + WC_SZ)

__device__ __align__(1024) char d_scratch[TOTAL_SCRATCH];

// ---------------- MMA building blocks ----------------
__device__ __forceinline__ u32 pack_bf16(float lo, float hi) {
    u32 r; asm("cvt.rn.bf16x2.f32 %0, %1, %2;" : "=r"(r) : "f"(hi), "f"(lo)); return r;
}
__device__ __forceinline__ unsigned short pack_e4m3(float lo, float hi) {
    unsigned short r;
    asm("cvt.rn.satfinite.e4m3x2.f32 %0, %1, %2;" : "=h"(r) : "f"(hi), "f"(lo));
    return r;
}
__device__ __forceinline__ float ex2(float x) {
    float r; asm("ex2.approx.f32 %0, %1;" : "=f"(r) : "f"(x)); return r;
}
__device__ __forceinline__ void cpasync16(u32 saddr, const void* g) {
    asm volatile("cp.async.cg.shared.global [%0], [%1], 16;" :: "r"(saddr), "l"(g));
}
#define CP_COMMIT() asm volatile("cp.async.commit_group;" ::: "memory")

__device__ __forceinline__ void ldsm_x4(u32 a, u32& r0, u32& r1, u32& r2, u32& r3) {
    asm volatile("ldmatrix.sync.aligned.m8n8.x4.shared.b16 {%0,%1,%2,%3}, [%4];"
                 : "=r"(r0), "=r"(r1), "=r"(r2), "=r"(r3) : "r"(a));
}
__device__ __forceinline__ void mma16816(float c[4], const u32 a[4], u32 b0, u32 b1) {
    asm volatile("mma.sync.aligned.m16n8k16.row.col.f32.bf16.bf16.f32 "
                 "{%0,%1,%2,%3}, {%4,%5,%6,%7}, {%8,%9}, {%0,%1,%2,%3};"
                 : "+f"(c[0]), "+f"(c[1]), "+f"(c[2]), "+f"(c[3])
                 : "r"(a[0]), "r"(a[1]), "r"(a[2]), "r"(a[3]), "r"(b0), "r"(b1));
}
__device__ __forceinline__ void mma16832_fp8(float c[4], const u32 a[4], u32 b0, u32 b1) {
    asm volatile("mma.sync.aligned.m16n8k32.row.col.f32.e4m3.e4m3.f32 "
                 "{%0,%1,%2,%3}, {%4,%5,%6,%7}, {%8,%9}, {%0,%1,%2,%3};"
                 : "+f"(c[0]), "+f"(c[1]), "+f"(c[2]), "+f"(c[3])
                 : "r"(a[0]), "r"(a[1]), "r"(a[2]), "r"(a[3]), "r"(b0), "r"(b1));
}

// Tile: 128 rows x 128 B. 8 x 16B chunks/row. Swizzle cc = c ^ (r&7).
#define TILE_B 16384
#define NSTAGE 3

__device__ __forceinline__ u32 sw64(int r, int ch) {
    return (u32)(r * 128 + ((ch ^ (r & 7)) << 4));
}

__device__ __forceinline__ void tile_load(u32 sdst, const char* src,
                                          size_t pitchB, int k0B, int tid) {
    int r = tid >> 1;
    const char* g = src + (size_t)r * pitchB + k0B;
#pragma unroll
    for (int i = 0; i < 4; i++) {
        int c = (tid & 1) * 4 + i;
        cpasync16(sdst + sw64(r, c), g + c * 16);
    }
}

// CTA 128x128 bf16 GEMM
__device__ __forceinline__ void hmma_gemm(
    u32 sA, u32 sB,
    const __nv_bfloat16* __restrict__ A, size_t pA,
    const __nv_bfloat16* __restrict__ B, size_t pB,
    int Kd, int tid, float acc[4][4][4])
{
#pragma unroll
    for (int i = 0; i < 4; i++)
#pragma unroll
        for (int j = 0; j < 4; j++)
#pragma unroll
            for (int e = 0; e < 4; e++) acc[i][j][e] = 0.f;

    const int lane = tid & 31, wid = tid >> 5;
    const int wm = wid & 1, wn = wid >> 1;
    const int T = Kd / 64;
    const char* Ab = (const char*)A;
    const char* Bb = (const char*)B;
    const size_t pAB = pA * 2, pBB = pB * 2;

    tile_load(sA, Ab, pAB, 0, tid);
    tile_load(sB, Bb, pBB, 0, tid);
    CP_COMMIT();
    if (T > 1) {
        tile_load(sA + TILE_B, Ab, pAB, 128, tid);
        tile_load(sB + TILE_B, Bb, pBB, 128, tid);
    }
    CP_COMMIT();

    int slot_next = 2 % NSTAGE;
    for (int t = 0; t < T; t++) {
        asm volatile("cp.async.wait_group 1;" ::: "memory");
        __syncthreads();
        if (t + 2 < T) {
            tile_load(sA + slot_next * TILE_B, Ab, pAB, (t + 2) * 128, tid);
            tile_load(sB + slot_next * TILE_B, Bb, pBB, (t + 2) * 128, tid);
        }
        CP_COMMIT();
        slot_next = (slot_next + 1 == NSTAGE) ? 0 : slot_next + 1;

        const int cur = t % NSTAGE;
        const u32 abuf = sA + cur * TILE_B;
        const u32 bbuf = sB + cur * TILE_B;
#pragma unroll
        for (int k16 = 0; k16 < 4; k16++) {
            u32 a[4][4];
#pragma unroll
            for (int f = 0; f < 4; f++) {
                int row = wm * 64 + f * 16 + (lane & 15);
                int ch  = k16 * 2 + (lane >> 4);
                ldsm_x4(abuf + sw64(row, ch), a[f][0], a[f][1], a[f][2], a[f][3]);
            }
            u32 b[4][2];
#pragma unroll
            for (int p = 0; p < 2; p++) {
                int row = wn * 32 + p * 16 + ((lane & 16) >> 1) + (lane & 7);
                int ch  = k16 * 2 + ((lane >> 3) & 1);
                ldsm_x4(bbuf + sw64(row, ch), b[2 * p][0], b[2 * p][1],
                        b[2 * p + 1][0], b[2 * p + 1][1]);
            }
#pragma unroll
            for (int mf = 0; mf < 4; mf++)
#pragma unroll
                for (int nf = 0; nf < 4; nf++)
                    mma16816(acc[mf][nf], a[mf], b[nf][0], b[nf][1]);
        }
    }
}

// CTA 128x128 FP8 GEMM (streamed K)
__device__ __forceinline__ void qmma_gemm(
    u32 sA, u32 sB,
    const char* __restrict__ A, size_t pAB,
    const char* __restrict__ B, size_t pBB,
    int KdB, int tid, float acc[4][4][4])
{
#pragma unroll
    for (int i = 0; i < 4; i++)
#pragma unroll
        for (int j = 0; j < 4; j++)
#pragma unroll
            for (int e = 0; e < 4; e++) acc[i][j][e] = 0.f;

    const int lane = tid & 31, wid = tid >> 5;
    const int wm = wid & 1, wn = wid >> 1;
    const int T = KdB / 128;

    tile_load(sA, A, pAB, 0, tid);
    tile_load(sB, B, pBB, 0, tid);
    CP_COMMIT();
    if (T > 1) {
        tile_load(sA + TILE_B, A, pAB, 128, tid);
        tile_load(sB + TILE_B, B, pBB, 128, tid);
    }
    CP_COMMIT();

    int slot_next = 2 % NSTAGE;
    for (int t = 0; t < T; t++) {
        asm volatile("cp.async.wait_group 1;" ::: "memory");
        __syncthreads();
        if (t + 2 < T) {
            tile_load(sA + slot_next * TILE_B, A, pAB, (t + 2) * 128, tid);
            tile_load(sB + slot_next * TILE_B, B, pBB, (t + 2) * 128, tid);
        }
        CP_COMMIT();
        slot_next = (slot_next + 1 == NSTAGE) ? 0 : slot_next + 1;

        const int cur = t % NSTAGE;
        const u32 abuf = sA + cur * TILE_B;
        const u32 bbuf = sB + cur * TILE_B;
#pragma unroll
        for (int k32 = 0; k32 < 4; k32++) {
            u32 a[4][4];
#pragma unroll
            for (int f = 0; f < 4; f++) {
                int row = wm * 64 + f * 16 + (lane & 15);
                int ch  = k32 * 2 + (lane >> 4);
                ldsm_x4(abuf + sw64(row, ch), a[f][0], a[f][1], a[f][2], a[f][3]);
            }
            u32 b[4][2];
#pragma unroll
            for (int p = 0; p < 2; p++) {
                int row = wn * 32 + p * 16 + ((lane & 16) >> 1) + (lane & 7);
                int ch  = k32 * 2 + ((lane >> 3) & 1);
                ldsm_x4(bbuf + sw64(row, ch), b[2 * p][0], b[2 * p][1],
                        b[2 * p + 1][0], b[2 * p + 1][1]);
            }
#pragma unroll
            for (int mf = 0; mf < 4; mf++)
#pragma unroll
                for (int nf = 0; nf < 4; nf++)
                    mma16832_fp8(acc[mf][nf], a[mf], b[nf][0], b[nf][1]);
        }
    }
}

#define SMEM_DYN   (2 * NSTAGE * TILE_B)   // 96 KB
#define SMEM_SCORE (6 * TILE_B)            // 96 KB: A + 3 B ring + 2 staging

// ============================ SIMT prep ============================
__global__ __launch_bounds__(256) void transpose_x(
    const float* __restrict__ x, const float* __restrict__ x_v,
    const float* __restrict__ x_h, __nv_bfloat16* __restrict__ xT)
{
    __shared__ float t[32][33];
    int z = blockIdx.z, tt = z >> 3, b = z & 7;
    const float* src = (tt == 0) ? x : (tt == 1 ? x_v : x_h);
    int n0 = blockIdx.x * 32, c0 = blockIdx.y * 32;
    int tx = threadIdx.x & 31, ty8 = threadIdx.x >> 5;
#pragma unroll
    for (int i = 0; i < 4; i++)
        t[ty8 + i * 8][tx] = src[((size_t)b * CIN + c0 + ty8 + i * 8) * NNE + n0 + tx];
    __syncthreads();
#pragma unroll
    for (int i = 0; i < 4; i++)
        xT[(((size_t)tt * BB + b) * NNE + n0 + ty8 + i * 8) * CIN + c0 + tx] =
            __float2bfloat16(t[tx][ty8 + i * 8]);
}

struct WC6 { const float* s[6]; };
__global__ __launch_bounds__(256) void conv_weights(WC6 w, __nv_bfloat16* __restrict__ dst,
                                                    float* __restrict__ Z)
{
    int idx = blockIdx.x * 256 + threadIdx.x;
    int t = idx >> 16, i = idx & 65535;
    dst[(size_t)t * 65536 + i] = __float2bfloat16(w.s[t][i]);
    if (idx < 2 * BB * NNE) Z[idx] = 0.f;
}

// gn8 = e4m3(g * 2048 / Z8)
__global__ __launch_bounds__(256) void gnorm(
    const __nv_bfloat16* __restrict__ g, const float* __restrict__ Z,
    unsigned char* __restrict__ gn8)
{
    size_t idx = ((size_t)blockIdx.x * 256 + threadIdx.x) * 2;
    int n = (int)(idx % NNE);
    size_t sb = idx / ((size_t)NNE * MIDC);
    const float* zr = Z + sb * NNE;
    float v0 = __bfloat162float(g[idx])     * __frcp_rn(zr[n])     * 2048.f;
    float v1 = __bfloat162float(g[idx + 1]) * __frcp_rn(zr[n + 1]) * 2048.f;
    *reinterpret_cast<unsigned short*>(gn8 + idx) = pack_e4m3(v0, v1);
}

// ============================ tensor kernels ============================

// Merged input convs. grid (18, BB, 5).
__global__ __launch_bounds__(256, 2) void k_inconv(
    const __nv_bfloat16* __restrict__ xT, const __nv_bfloat16* __restrict__ Wc,
    const float* __restrict__ ba, const float* __restrict__ ga, const float* __restrict__ ta,
    const float* __restrict__ bv, const float* __restrict__ gv, const float* __restrict__ tv,
    const float* __restrict__ bgav, const float* __restrict__ bgah,
    unsigned char* __restrict__ ft, __nv_bfloat16* __restrict__ g)
{
    extern __shared__ char dsm[];
    __shared__ float sS[128], sC[128];
    int tid = threadIdx.x, lane = tid & 31, wid = tid >> 5;
    int wm = wid & 1, wn = wid >> 1;
    int nt = blockIdx.x, b = blockIdx.y, o = blockIdx.z;

    if (o < 3 && tid < 128) {
        const float* bias  = (o == 0) ? ba : bv;
        const float* gamma = (o == 0) ? ga : gv;
        const float* beta  = (o == 0) ? ta : tv;
        float s = gamma[tid] * rsqrtf(1.f + 1e-5f);
        sS[tid] = s; sC[tid] = bias[tid] * s + beta[tid];
    }

    const __nv_bfloat16* A;
    const __nv_bfloat16* B;
    if (o < 3) {
        A = xT + (((size_t)o * BB + b) * NNE + (size_t)nt * 128) * CIN;
        B = Wc + (size_t)((o == 0) ? 0 : 1) * 65536;
    } else {
        A = Wc + (size_t)(2 + (o - 3)) * 65536;
        B = xT + ((size_t)b * NNE + (size_t)nt * 128) * CIN;
    }

    float acc[4][4][4];
    u32 sA = (u32)__cvta_generic_to_shared(dsm);
    u32 sB = sA + NSTAGE * TILE_B;
    hmma_gemm(sA, sB, A, CIN, B, CIN, CIN, tid, acc);

    if (o < 3) {
        unsigned char* dst = ft + (size_t)o * (size_t)BB * NNE * MIDC
                                + ((size_t)b * NNE + (size_t)nt * 128) * MIDC;
        const bool even = ((lane & 1) == 0);
#pragma unroll
        for (int mf = 0; mf < 4; mf++)
#pragma unroll
            for (int nf = 0; nf < 4; nf++)
#pragma unroll
                for (int h = 0; h < 2; h++) {
                    int r = wm * 64 + mf * 16 + (lane >> 2) + h * 8;
                    int c = wn * 32 + nf * 8 + ((lane & 3) << 1);
                    float y0 = fmaxf(acc[mf][nf][h * 2]     * sS[c]     + sC[c],     0.f);
                    float y1 = fmaxf(acc[mf][nf][h * 2 + 1] * sS[c + 1] + sC[c + 1], 0.f);
                    u32 mine = (u32)pack_e4m3(y0, y1);
                    u32 other = __shfl_xor_sync(0xffffffffu, mine, 1);
                    if (even)
                        *reinterpret_cast<u32*>(dst + (size_t)r * MIDC + c) =
                            mine | (other << 16);
                }
    } else {
        const float* bias = (o == 3) ? bgav : bgah;
        __nv_bfloat16* dst = g + (size_t)((o - 3) * BB + b) * MIDC * NNE + (size_t)nt * 128;
#pragma unroll
        for (int mf = 0; mf < 4; mf++)
#pragma unroll
            for (int nf = 0; nf < 4; nf++)
#pragma unroll
                for (int h = 0; h < 2; h++) {
                    int r = wm * 64 + mf * 16 + (lane >> 2) + h * 8;
                    int c = wn * 32 + nf * 8 + ((lane & 3) << 1);
                    float bval = bias[r];
                    *reinterpret_cast<u32*>(dst + (size_t)r * NNE + c) =
                        pack_bf16(acc[mf][nf][h * 2] + bval, acc[mf][nf][h * 2 + 1] + bval);
                }
    }
}

// Pipelined score kernel with smem-staged output.
// ET8 = exp2(S*C2FOLD - 3); Z8 += column sums. grid (jt 18, b + 8*sel)
__global__ __launch_bounds__(256, 2) void k_score(
    const unsigned char* __restrict__ ft, unsigned char* __restrict__ et,
    float* __restrict__ Z)
{
    extern __shared__ char dsm[];
    __shared__ float zs[2][2][128];
    int tid = threadIdx.x, lane = tid & 31, wid = tid >> 5;
    int wm = wid & 1, wn = wid >> 1;
    int jt = blockIdx.x;
    int z = blockIdx.y, b = z & 7, sel = z >> 3;

    const char* fa = (const char*)ft + (size_t)b * NNE * MIDC + (size_t)jt * 128 * MIDC;
    const char* fq = (const char*)ft + (size_t)(1 + sel) * (size_t)BB * NNE * MIDC
                                     + (size_t)b * NNE * MIDC;

    u32 sA   = (u32)__cvta_generic_to_shared(dsm);  // resident fa_j
    u32 sB   = sA + TILE_B;                         // 3 ring slots
    u32 sStg = sA + 4 * TILE_B;                     // 2 staging slots

    tile_load(sA, fa, MIDC, 0, tid);
    CP_COMMIT();
    tile_load(sB, fq, MIDC, 0, tid);
    CP_COMMIT();
    tile_load(sB + TILE_B, fq + (size_t)128 * MIDC, MIDC, 0, tid);
    CP_COMMIT();

    unsigned char* dstBase = et + ((size_t)(sel * BB + b) * NNE + (size_t)jt * 128) * NNE;
    float* Zrow = Z + (size_t)(sel * BB + b) * NNE;

    // output readback mapping: thread covers rows (tid>>3)+p*32, chunk tid&7
    const int rrow = tid >> 3, rch = tid & 7;
    unsigned char* pr[4];
#pragma unroll
    for (int p = 0; p < 4; p++)
        pr[p] = dstBase + (size_t)(rrow + p * 32) * NNE + rch * 16;
    u32 rdo[4];
#pragma unroll
    for (int p = 0; p < 4; p++) {
        int row = rrow + p * 32;
        rdo[p] = (u32)(row * 128 + ((rch ^ (row & 7)) << 4));
    }
    // STS offsets: r = wm*64+mf*16+(lane>>2)+h*8 ; byte col cb = wn*32+nf*8+(lane&3)*2
    const int rb0 = wm * 64 + (lane >> 2);
    const int cb0 = wn * 32 + ((lane & 3) << 1);

    for (int it = 0; it < 18; it++) {
        asm volatile("cp.async.wait_group 1;" ::: "memory");
        __syncthreads();
        if (it + 2 < 18)
            tile_load(sB + ((it + 2) % 3) * TILE_B,
                      fq + (size_t)(it + 2) * 128 * MIDC, MIDC, 0, tid);
        CP_COMMIT();

        const u32 bbuf = sB + (it % 3) * TILE_B;
        float acc[4][4][4];
#pragma unroll
        for (int i = 0; i < 4; i++)
#pragma unroll
            for (int j = 0; j < 4; j++)
#pragma unroll
                for (int e = 0; e < 4; e++) acc[i][j][e] = 0.f;

#pragma unroll
        for (int k32 = 0; k32 < 4; k32++) {
            u32 a[4][4];
#pragma unroll
            for (int f = 0; f < 4; f++) {
                int row = wm * 64 + f * 16 + (lane & 15);
                int ch  = k32 * 2 + (lane >> 4);
                ldsm_x4(sA + sw64(row, ch), a[f][0], a[f][1], a[f][2], a[f][3]);
            }
            u32 bfr[4][2];
#pragma unroll
            for (int p = 0; p < 2; p++) {
                int row = wn * 32 + p * 16 + ((lane & 16) >> 1) + (lane & 7);
                int ch  = k32 * 2 + ((lane >> 3) & 1);
                ldsm_x4(bbuf + sw64(row, ch), bfr[2 * p][0], bfr[2 * p][1],
                        bfr[2 * p + 1][0], bfr[2 * p + 1][1]);
            }
#pragma unroll
            for (int mf = 0; mf < 4; mf++)
#pragma unroll
                for (int nf = 0; nf < 4; nf++)
                    mma16832_fp8(acc[mf][nf], a[mf], bfr[nf][0], bfr[nf][1]);
        }

        // fused exp2
#pragma unroll
        for (int mf = 0; mf < 4; mf++)
#pragma unroll
            for (int nf = 0; nf < 4; nf++)
#pragma unroll
                for (int e = 0; e < 4; e++)
                    acc[mf][nf][e] = ex2(fmaf(acc[mf][nf][e], C2FOLD, -3.0f));

        // stage fp8 tile in smem (no shuffles)
        const u32 stg = sStg + (it & 1) * TILE_B;
#pragma unroll
        for (int mf = 0; mf < 4; mf++)
#pragma unroll
            for (int nf = 0; nf < 4; nf++)
#pragma unroll
                for (int h = 0; h < 2; h++) {
                    int r  = rb0 + mf * 16 + h * 8;
                    int cb = cb0 + nf * 8;
                    u32 so = stg + (u32)(r * 128 + (((cb >> 4) ^ (r & 7)) << 4) + (cb & 15));
                    unsigned short v = pack_e4m3(acc[mf][nf][h * 2], acc[mf][nf][h * 2 + 1]);
                    asm volatile("st.shared.u16 [%0], %1;" :: "r"(so), "h"(v));
                }

        // Z column sums (registers)
        const int zb = it & 1;
#pragma unroll
        for (int nf = 0; nf < 4; nf++) {
            float s0 = 0.f, s1 = 0.f;
#pragma unroll
            for (int mf = 0; mf < 4; mf++) {
                s0 += acc[mf][nf][0] + acc[mf][nf][2];
                s1 += acc[mf][nf][1] + acc[mf][nf][3];
            }
#pragma unroll
            for (int off = 4; off < 32; off <<= 1) {
                s0 += __shfl_xor_sync(0xffffffffu, s0, off);
                s1 += __shfl_xor_sync(0xffffffffu, s1, off);
            }
            if (lane < 4) {
                int c = wn * 32 + nf * 8 + lane * 2;
                zs[zb][wm][c] = s0;
                zs[zb][wm][c + 1] = s1;
            }
        }
        __syncthreads();   // covers zs AND staging tile

        if (tid < 128)
            atomicAdd(&Zrow[(size_t)it * 128 + tid], zs[zb][0][tid] + zs[zb][1][tid]);

        // coalesced readback -> global (4 x 128B lines per warp-instr)
#pragma unroll
        for (int p = 0; p < 4; p++) {
            uint4 v;
            asm volatile("ld.shared.v4.b32 {%0,%1,%2,%3}, [%4];"
                         : "=r"(v.x), "=r"(v.y), "=r"(v.z), "=r"(v.w)
                         : "r"(stg + rdo[p]));
            *reinterpret_cast<uint4*>(pr[p] + (size_t)it * 128) = v;
        }
    }
}

// oT[sel][b][j][m] = (1/2048) * sum_i ET8[j][i]·gn8[m][i]. grid (jt 18, 1, b+8*sel).
__global__ __launch_bounds__(256, 2) void k_ogemm(
    const unsigned char* __restrict__ et, const unsigned char* __restrict__ gn8,
    __nv_bfloat16* __restrict__ oT)
{
    extern __shared__ char dsm[];
    int tid = threadIdx.x, lane = tid & 31, wid = tid >> 5;
    int wm = wid & 1, wn = wid >> 1;
    int jt = blockIdx.x;
    int z = blockIdx.z, b = z & 7, sel = z >> 3;

    const char* A = (const char*)et + ((size_t)(sel * BB + b) * NNE + (size_t)jt * 128) * NNE;
    const char* B = (const char*)gn8 + (size_t)(sel * BB + b) * MIDC * NNE;

    float acc[4][4][4];
    u32 sA = (u32)__cvta_generic_to_shared(dsm);
    u32 sB = sA + NSTAGE * TILE_B;
    qmma_gemm(sA, sB, A, NNE, B, NNE, NNE, tid, acc);

    __nv_bfloat16* dst = oT + ((size_t)(sel * BB + b) * NNE + (size_t)jt * 128) * MIDC;
#pragma unroll
    for (int mf = 0; mf < 4; mf++)
#pragma unroll
        for (int nf = 0; nf < 4; nf++)
#pragma unroll
            for (int h = 0; h < 2; h++) {
                int r = wm * 64 + mf * 16 + (lane >> 2) + h * 8;
                int c = wn * 32 + nf * 8 + ((lane & 3) << 1);
                *reinterpret_cast<u32*>(dst + (size_t)r * MIDC + c) =
                    pack_bf16(acc[mf][nf][h * 2] * INV_OSCALE,
                              acc[mf][nf][h * 2 + 1] * INV_OSCALE);
            }
}

// out[sel][b][cout][n] = Wf·oT^T + bias + x. grid (nt 18, ct 4, b+8*sel).
__global__ __launch_bounds__(256, 2) void k_outconv(
    const __nv_bfloat16* __restrict__ Wc, const __nv_bfloat16* __restrict__ oT,
    const float* __restrict__ bfav, const float* __restrict__ bfah,
    const float* __restrict__ x,
    float* __restrict__ out_v, float* __restrict__ out_h)
{
    extern __shared__ char dsm[];
    int tid = threadIdx.x, lane = tid & 31, wid = tid >> 5;
    int wm = wid & 1, wn = wid >> 1;
    int nt = blockIdx.x, ct = blockIdx.y;
    int z = blockIdx.z, b = z & 7, sel = z >> 3;

    const __nv_bfloat16* A = Wc + (size_t)(4 + sel) * 65536 + (size_t)ct * 128 * MIDC;
    const __nv_bfloat16* B = oT + ((size_t)(sel * BB + b) * NNE + (size_t)nt * 128) * MIDC;

    float acc[4][4][4];
    u32 sA = (u32)__cvta_generic_to_shared(dsm);
    u32 sB = sA + NSTAGE * TILE_B;
    hmma_gemm(sA, sB, A, MIDC, B, MIDC, MIDC, tid, acc);

    const float* bias = (sel == 0) ? bfav : bfah;
    float* outp = (sel == 0) ? out_v : out_h;
#pragma unroll
    for (int mf = 0; mf < 4; mf++)
#pragma unroll
        for (int nf = 0; nf < 4; nf++)
#pragma unroll
            for (int h = 0; h < 2; h++) {
                int r = wm * 64 + mf * 16 + (lane >> 2) + h * 8;
                int c = wn * 32 + nf * 8 + ((lane & 3) << 1);
                int cout = ct * 128 + r;
                size_t base = ((size_t)b * CIN + cout) * NNE + (size_t)nt * 128 + c;
                float2 xv = *reinterpret_cast<const float2*>(x + base);
                float bval = bias[cout];
                *reinterpret_cast<float2*>(outp + base) =
                    make_float2(acc[mf][nf][h * 2] + bval + xv.x,
                                acc[mf][nf][h * 2 + 1] + bval + xv.y);
            }
}

// ============================================================================
extern "C" void kernel_launch(void* const* d_in, const int* in_sizes, int n_in,
                              void* d_out, int out_size)
{
    (void)in_sizes; (void)n_in; (void)out_size;

    const float* x    = (const float*)d_in[0];
    const float* x_h  = (const float*)d_in[1];
    const float* x_v  = (const float*)d_in[2];
    const float* Wa   = (const float*)d_in[3];
    const float* ba   = (const float*)d_in[4];
    const float* ga   = (const float*)d_in[5];
    const float* ta   = (const float*)d_in[6];
    const float* Wv   = (const float*)d_in[7];
    const float* bv   = (const float*)d_in[8];
    const float* gv   = (const float*)d_in[9];
    const float* tv   = (const float*)d_in[10];
    const float* Wgav = (const float*)d_in[11];
    const float* bgav = (const float*)d_in[12];
    const float* Wgah = (const float*)d_in[13];
    const float* bgah = (const float*)d_in[14];
    const float* Wfav = (const float*)d_in[15];
    const float* bfav = (const float*)d_in[16];
    const float* Wfah = (const float*)d_in[17];
    const float* bfah = (const float*)d_in[18];

    void* sp = nullptr;
    cudaGetSymbolAddress(&sp, d_scratch);
    char* base = (char*)sp;
    __nv_bfloat16* xT  = (__nv_bfloat16*)(base + XT_OFF);
    unsigned char* ft  = (unsigned char*)(base + FT_OFF);
    __nv_bfloat16* g   = (__nv_bfloat16*)(base + G_OFF);
    unsigned char* gn8 = (unsigned char*)(base + GN_OFF);
    unsigned char* et  = (unsigned char*)(base + ET_OFF);
    float*         Zp  = (float*)(base + Z_OFF);
    __nv_bfloat16* oT  = (__nv_bfloat16*)(base + OT_OFF);
    __nv_bfloat16* Wc  = (__nv_bfloat16*)(base + WC_OFF);

    float* out_h = (float*)d_out;
    float* out_v = out_h + (size_t)BB * CIN * NNE;

    static int attr_done = 0;
    if (!attr_done) {
        cudaFuncSetAttribute(k_inconv,  cudaFuncAttributeMaxDynamicSharedMemorySize, SMEM_DYN);
        cudaFuncSetAttribute(k_score,   cudaFuncAttributeMaxDynamicSharedMemorySize, SMEM_SCORE);
        cudaFuncSetAttribute(k_ogemm,   cudaFuncAttributeMaxDynamicSharedMemorySize, SMEM_DYN);
        cudaFuncSetAttribute(k_outconv, cudaFuncAttributeMaxDynamicSharedMemorySize, SMEM_DYN);
        attr_done = 1;
    }

    // prep
    transpose_x<<<dim3(NNE / 32, CIN / 32, 3 * BB), 256>>>(x, x_v, x_h, xT);
    WC6 w = {{ Wa, Wv, Wgav, Wgah, Wfav, Wfah }};
    conv_weights<<<1536, 256>>>(w, Wc, Zp);

    // all 5 input convs in one launch
    k_inconv<<<dim3(18, BB, 5), 256, SMEM_DYN>>>(xT, Wc, ba, ga, ta, bv, gv, tv,
                                                 bgav, bgah, ft, g);

    // scores: pipelined FP8 GEMM, smem-staged output
    k_score<<<dim3(18, 16), 256, SMEM_SCORE>>>(ft, et, Zp);

    // fold 2048/Z8 into g -> e4m3
    gnorm<<<(2 * BB * MIDC * NNE) / 512, 256>>>(g, Zp, gn8);

    // oT = (ET8 · gn8^T) / 2048
    k_ogemm<<<dim3(18, 1, 16), 256, SMEM_DYN>>>(et, gn8, oT);

    // output convs + residual
    k_outconv<<<dim3(18, 4, 16), 256, SMEM_DYN>>>(Wc, oT, bfav, bfah, x, out_v, out_h);
}